// round 1
// baseline (speedup 1.0000x reference)
#include <cuda_runtime.h>
#include <math.h>

// Problem constants
#define CB  32
#define CS  512
#define CE  512
#define CDK 128
#define CH  6
#define CD2 1024
#define CHD 768   // H*DK

// ---------------- scratch layout (single __device__ global) ----------------
constexpr long SZ_XP  = (long)CB*CS*CE;          // 8,388,608
constexpr long SZ_QKV = (long)CB*CH*CS*CDK;      // 12,582,912
constexpr long SZ_SC  = (long)CB*CH*CS*CS;       // 50,331,648
constexpr long SZ_Z   = (long)CB*CS*CHD;         // 12,582,912
constexpr long SZ_BD  = (long)CB*CS*CD2;         // 16,777,216
constexpr long SZ_POS = (long)CS*CE;             // 262,144

constexpr long OFF_XP  = 0;
constexpr long OFF_Q   = OFF_XP  + SZ_XP;
constexpr long OFF_K   = OFF_Q   + SZ_QKV;
constexpr long OFF_V   = OFF_K   + SZ_QKV;
constexpr long OFF_SC  = OFF_V   + SZ_QKV;
constexpr long OFF_Z   = OFF_SC  + SZ_SC;
constexpr long OFF_A   = OFF_Z   + SZ_Z;
constexpr long OFF_N1  = OFF_A   + SZ_BD;
constexpr long OFF_F   = OFF_N1  + SZ_BD;
constexpr long OFF_N2  = OFF_F   + SZ_BD;
constexpr long OFF_N3  = OFF_N2  + SZ_BD;
constexpr long OFF_POS = OFF_N3  + SZ_BD;
constexpr long SCRATCH_TOT = OFF_POS + SZ_POS;   // ~193.2M floats (~737 MB)

__device__ float g_scratch[SCRATCH_TOT];

// ---------------- positional encoding ----------------
// Faithful to the reference's integer-division exponent:
// for column e, m=e/2: exponent = 0 if m<128 else 1  -> denom 1.0 or 10000.0
__global__ void posgen_kernel(float* __restrict__ pos) {
    int idx = blockIdx.x * blockDim.x + threadIdx.x;
    if (idx >= CS * CE) return;
    int s = idx >> 9;        // / 512
    int e = idx & 511;
    int m = e >> 1;
    double ang = (m >= 128) ? ((double)s / 10000.0) : (double)s;
    pos[idx] = (e & 1) ? (float)cos(ang) : (float)sin(ang);
}

__global__ void addpos_kernel(const float* __restrict__ X,
                              const float* __restrict__ pos,
                              float* __restrict__ xp, long n) {
    long idx = (long)blockIdx.x * blockDim.x + threadIdx.x;
    if (idx >= n) return;
    xp[idx] = X[idx] + pos[idx % (CS * CE)];
}

// ---------------- generic batched tiled GEMM (fp32) ----------------
// C[z] = alpha * A[z] @ op(B[z]) + bias[z]  (optional tanh)
// z decomposed as z = zb*Hdiv + zh. All dims assumed multiples of tile sizes.
#define BM 64
#define BN 64
#define BKK 16

template<bool TRANSB, bool DOTANH>
__global__ __launch_bounds__(256) void gemm_k(
    const float* __restrict__ Ab, const float* __restrict__ Bb,
    const float* __restrict__ biasb, float* __restrict__ Cb,
    int K, int lda, int ldb, int ldc,
    int Hdiv,
    long sA_b, long sA_h, long sB_b, long sB_h,
    long sC_b, long sC_h, long sBias_h,
    float alpha)
{
    int z  = blockIdx.z;
    int zb = z / Hdiv;
    int zh = z - zb * Hdiv;
    const float* A  = Ab + zb * sA_b + zh * sA_h;
    const float* Bp = Bb + zb * sB_b + zh * sB_h;
    float*       C  = Cb + zb * sC_b + zh * sC_h;

    int m0 = blockIdx.y * BM;
    int n0 = blockIdx.x * BN;
    int tid = threadIdx.x;

    __shared__ __align__(16) float As[BKK][BM];
    __shared__ __align__(16) float Bs[BKK][BN];

    float acc[4][4] = {};
    int tx = tid & 15;
    int ty = tid >> 4;

    // loaders: 1024 floats per tile, 256 threads * float4
    int a_r = tid >> 2;            // 0..63
    int a_c = (tid & 3) * 4;       // 0,4,8,12
    int b_r = tid >> 4;            // 0..15
    int b_c = (tid & 15) * 4;      // 0..60

    for (int k0 = 0; k0 < K; k0 += BKK) {
        float4 av = *(const float4*)(A + (long)(m0 + a_r) * lda + k0 + a_c);
        As[a_c + 0][a_r] = av.x;
        As[a_c + 1][a_r] = av.y;
        As[a_c + 2][a_r] = av.z;
        As[a_c + 3][a_r] = av.w;
        if (TRANSB) {
            float4 bv = *(const float4*)(Bp + (long)(n0 + a_r) * ldb + k0 + a_c);
            Bs[a_c + 0][a_r] = bv.x;
            Bs[a_c + 1][a_r] = bv.y;
            Bs[a_c + 2][a_r] = bv.z;
            Bs[a_c + 3][a_r] = bv.w;
        } else {
            float4 bv = *(const float4*)(Bp + (long)(k0 + b_r) * ldb + n0 + b_c);
            *(float4*)(&Bs[b_r][b_c]) = bv;
        }
        __syncthreads();
        #pragma unroll
        for (int kk = 0; kk < BKK; ++kk) {
            float4 a4 = *(const float4*)(&As[kk][ty * 4]);
            float4 b4 = *(const float4*)(&Bs[kk][tx * 4]);
            float ar[4] = {a4.x, a4.y, a4.z, a4.w};
            float br[4] = {b4.x, b4.y, b4.z, b4.w};
            #pragma unroll
            for (int i = 0; i < 4; ++i)
                #pragma unroll
                for (int j = 0; j < 4; ++j)
                    acc[i][j] = fmaf(ar[i], br[j], acc[i][j]);
        }
        __syncthreads();
    }

    const float* bias = biasb ? (biasb + (long)zh * sBias_h) : nullptr;
    #pragma unroll
    for (int i = 0; i < 4; ++i) {
        long row = (long)(m0 + ty * 4 + i) * ldc + n0 + tx * 4;
        float vals[4];
        #pragma unroll
        for (int j = 0; j < 4; ++j) {
            float v = acc[i][j] * alpha;
            if (bias) v += bias[n0 + tx * 4 + j];
            if (DOTANH) v = tanhf(v);
            vals[j] = v;
        }
        float4 o;
        o.x = vals[0]; o.y = vals[1]; o.z = vals[2]; o.w = vals[3];
        *(float4*)(C + row) = o;
    }
}

// ---------------- softmax over the QUERY axis (axis s) ----------------
// scores layout (z, s, t), z = b*H+h. Normalize over s for each (z,t).
__global__ void softmax_q_kernel(float* __restrict__ Sc) {
    long base = (long)blockIdx.x * CS * CS;
    int t = threadIdx.x;          // 512 threads, one column each
    float mx = -1e30f;
    for (int s = 0; s < CS; ++s)
        mx = fmaxf(mx, Sc[base + (long)s * CS + t]);
    float sum = 0.f;
    for (int s = 0; s < CS; ++s)
        sum += expf(Sc[base + (long)s * CS + t] - mx);
    float inv = 1.f / sum;
    for (int s = 0; s < CS; ++s) {
        long idx = base + (long)s * CS + t;
        Sc[idx] = expf(Sc[idx] - mx) * inv;
    }
}

// ---------------- batch-norm over axis 0 (batch), fused residual add ------
// out[b, j] = ((x[b,j] + add[b, s, e % addw]) - mean_b) / sqrt(var_b + 1e-3)
// j in [0, S*D2); addw in {512, 1024} (power of two).
__global__ void bn_kernel(const float* __restrict__ x,
                          const float* __restrict__ add,
                          int addw,
                          float* __restrict__ out) {
    int j = blockIdx.x * blockDim.x + threadIdx.x;
    if (j >= CS * CD2) return;
    const long SD = (long)CS * CD2;
    int s  = j >> 10;        // / 1024
    int e  = j & 1023;
    int ae = e & (addw - 1);
    long aoff = (long)s * addw + ae;

    float v[CB];
    float sum = 0.f;
    #pragma unroll
    for (int b = 0; b < CB; ++b) {
        float t = x[(long)b * SD + j] + add[(long)b * CS * addw + aoff];
        v[b] = t;
        sum += t;
    }
    float mean = sum * (1.f / CB);
    float var = 0.f;
    #pragma unroll
    for (int b = 0; b < CB; ++b) {
        float d = v[b] - mean;
        var += d * d;
    }
    var *= (1.f / CB);
    float rstd = rsqrtf(var + 1e-3f);
    #pragma unroll
    for (int b = 0; b < CB; ++b)
        out[(long)b * SD + j] = (v[b] - mean) * rstd;
}

// ---------------- host-side attention layer ----------------
static void run_attn(const float* xin, int Din,
                     const float* Wq, const float* Wk, const float* Wv,
                     const float* bq, const float* bk, const float* bv,
                     const float* Wo, const float* bo,
                     float* q, float* k, float* v, float* sc, float* z,
                     float* aout)
{
    dim3 blk(256);
    // QKV projections: per (b,h): (S, Din) @ (Din, DK)
    dim3 gq(CDK / BN, CS / BM, CB * CH);
    long sAb = (long)CS * Din;
    long sBh = (long)Din * CDK;
    long sCb = (long)CH * CS * CDK;
    long sCh = (long)CS * CDK;
    gemm_k<false, false><<<gq, blk>>>(xin, Wq, bq, q, Din, Din, CDK, CDK,
                                      CH, sAb, 0, 0, sBh, sCb, sCh, CDK, 1.f);
    gemm_k<false, false><<<gq, blk>>>(xin, Wk, bk, k, Din, Din, CDK, CDK,
                                      CH, sAb, 0, 0, sBh, sCb, sCh, CDK, 1.f);
    gemm_k<false, false><<<gq, blk>>>(xin, Wv, bv, v, Din, Din, CDK, CDK,
                                      CH, sAb, 0, 0, sBh, sCb, sCh, CDK, 1.f);

    // scores: per z: (S, DK) @ (S, DK)^T, scaled by 1/sqrt(DK)
    dim3 gs(CS / BN, CS / BM, CB * CH);
    gemm_k<true, false><<<gs, blk>>>(q, k, nullptr, sc, CDK, CDK, CDK, CS,
                                     1, (long)CS * CDK, 0, (long)CS * CDK, 0,
                                     (long)CS * CS, 0, 0,
                                     0.08838834764831845f);

    // softmax over query axis
    softmax_q_kernel<<<CB * CH, CS>>>(sc);

    // o = attn @ v, written directly in (b, s, h, k) layout -> z (ldc = 768)
    dim3 ga(CDK / BN, CS / BM, CB * CH);
    gemm_k<false, false><<<ga, blk>>>(sc, v, nullptr, z, CS, CS, CDK, CHD,
                                      CH,
                                      (long)CH * CS * CS, (long)CS * CS,
                                      (long)CH * CS * CDK, (long)CS * CDK,
                                      (long)CS * CHD, 128, 0, 1.f);

    // output projection: (B*S, 768) @ (768, 1024)
    dim3 go(CD2 / BN, (CB * CS) / BM, 1);
    gemm_k<false, false><<<go, blk>>>(z, Wo, bo, aout, CHD, CHD, CD2, CD2,
                                      1, 0, 0, 0, 0, 0, 0, 0, 1.f);
}

extern "C" void kernel_launch(void* const* d_in, const int* in_sizes, int n_in,
                              void* d_out, int out_size)
{
    const float* X    = (const float*)d_in[0];
    const float* Wq1  = (const float*)d_in[1];
    const float* Wk1  = (const float*)d_in[2];
    const float* Wv1  = (const float*)d_in[3];
    const float* bq1  = (const float*)d_in[4];
    const float* bk1  = (const float*)d_in[5];
    const float* bv1  = (const float*)d_in[6];
    const float* Wo1  = (const float*)d_in[7];
    const float* bo1  = (const float*)d_in[8];
    const float* Wff1 = (const float*)d_in[9];
    const float* bff1 = (const float*)d_in[10];
    const float* Wq2  = (const float*)d_in[11];
    const float* Wk2  = (const float*)d_in[12];
    const float* Wv2  = (const float*)d_in[13];
    const float* bq2  = (const float*)d_in[14];
    const float* bk2  = (const float*)d_in[15];
    const float* bv2  = (const float*)d_in[16];
    const float* Wo2  = (const float*)d_in[17];
    const float* bo2  = (const float*)d_in[18];
    const float* Wff2 = (const float*)d_in[19];
    const float* bff2 = (const float*)d_in[20];
    float* out = (float*)d_out;

    float* sb = nullptr;
    cudaGetSymbolAddress((void**)&sb, g_scratch);
    float* xp  = sb + OFF_XP;
    float* q   = sb + OFF_Q;
    float* k   = sb + OFF_K;
    float* v   = sb + OFF_V;
    float* sc  = sb + OFF_SC;
    float* z   = sb + OFF_Z;
    float* a   = sb + OFF_A;
    float* n1  = sb + OFF_N1;
    float* f   = sb + OFF_F;
    float* n2  = sb + OFF_N2;
    float* n3  = sb + OFF_N3;
    float* pos = sb + OFF_POS;

    // positional encoding + residual-cat source
    posgen_kernel<<<(CS * CE + 255) / 256, 256>>>(pos);
    long nxp = (long)CB * CS * CE;
    addpos_kernel<<<(unsigned)((nxp + 255) / 256), 256>>>(X, pos, xp, nxp);

    dim3 blk(256);
    dim3 gff(CD2 / BN, (CB * CS) / BM, 1);
    int nbn = (CS * CD2 + 255) / 256;

    // block 1: attention (input width 512)
    run_attn(xp, CE, Wq1, Wk1, Wv1, bq1, bk1, bv1, Wo1, bo1,
             q, k, v, sc, z, a);
    // n1 = BN(attn + concat(xp, xp))
    bn_kernel<<<nbn, 256>>>(a, xp, CE, n1);

    // block 2: FFN
    gemm_k<false, true><<<gff, blk>>>(n1, Wff1, bff1, f, CD2, CD2, CD2, CD2,
                                      1, 0, 0, 0, 0, 0, 0, 0, 1.f);
    bn_kernel<<<nbn, 256>>>(f, n1, CD2, n2);

    // block 3: attention (input width 1024)
    run_attn(n2, CD2, Wq2, Wk2, Wv2, bq2, bk2, bv2, Wo2, bo2,
             q, k, v, sc, z, a);
    bn_kernel<<<nbn, 256>>>(a, n2, CD2, n3);

    // block 4: FFN
    gemm_k<false, true><<<gff, blk>>>(n3, Wff2, bff2, f, CD2, CD2, CD2, CD2,
                                      1, 0, 0, 0, 0, 0, 0, 0, 1.f);
    bn_kernel<<<nbn, 256>>>(f, n3, CD2, out);
}

// round 2
// speedup vs baseline: 1.9891x; 1.9891x over previous
#include <cuda_runtime.h>
#include <cuda_bf16.h>
#include <cstdint>
#include <math.h>

#define CB 32
#define CS 512
#define CE 512
#define CDK 128
#define CH 6
#define CD2 1024
#define CHD 768

// ---------------- sizes (elements) ----------------
constexpr long NB_XP  = (long)CB*CS*CE;        // 8,388,608
constexpr long NB_QKV = (long)CB*CH*CS*CDK;    // 12,582,912
constexpr long NB_SC  = (long)CB*CH*CS*CS;     // 50,331,648
constexpr long NB_Z   = (long)CB*CS*CHD;       // 12,582,912
constexpr long NB_D2  = (long)CB*CS*CD2;       // 16,777,216
constexpr long NW_QKV1 = (long)CH*CE*CDK;      // 393,216
constexpr long NW_QKV2 = (long)CH*CD2*CDK;     // 786,432
constexpr long NW_O   = (long)CHD*CD2;         // 786,432
constexpr long NW_F   = (long)CD2*CD2;         // 1,048,576

// ---------------- f32 scratch offsets (floats) ----------------
constexpr long OF_POS = 0;
constexpr long OF_XP  = OF_POS + (long)CS*CE;
constexpr long OF_V   = OF_XP + NB_XP;
constexpr long OF_SC  = OF_V + NB_QKV;
constexpr long OF_A   = OF_SC + NB_SC;
constexpr long OF_N1  = OF_A + NB_D2;
constexpr long OF_N2  = OF_N1 + NB_D2;
constexpr long OF_N3  = OF_N2 + NB_D2;
constexpr long OF_F   = OF_N3 + NB_D2;
constexpr long F32_END = OF_F + NB_D2;

// ---------------- bf16 scratch offsets (bf16 elems) ----------------
constexpr long HB_XPH = 0;
constexpr long HB_XPL = HB_XPH + NB_XP;
constexpr long HB_QH  = HB_XPL + NB_XP;
constexpr long HB_QL  = HB_QH + NB_QKV;
constexpr long HB_KH  = HB_QL + NB_QKV;
constexpr long HB_KL  = HB_KH + NB_QKV;
constexpr long HB_VTH = HB_KL + NB_QKV;
constexpr long HB_VTL = HB_VTH + NB_QKV;
constexpr long HB_ATH = HB_VTL + NB_QKV;
constexpr long HB_ATL = HB_ATH + NB_SC;
constexpr long HB_ZH  = HB_ATL + NB_SC;
constexpr long HB_ZL  = HB_ZH + NB_Z;
constexpr long HB_N1H = HB_ZL + NB_Z;
constexpr long HB_N1L = HB_N1H + NB_D2;
constexpr long HB_N2H = HB_N1L + NB_D2;
constexpr long HB_N2L = HB_N2H + NB_D2;
constexpr long HB_N3H = HB_N2L + NB_D2;
constexpr long HB_N3L = HB_N3H + NB_D2;
constexpr long HB_W1QH = HB_N3L + NB_D2;
constexpr long HB_W1QL = HB_W1QH + NW_QKV1;
constexpr long HB_W1KH = HB_W1QL + NW_QKV1;
constexpr long HB_W1KL = HB_W1KH + NW_QKV1;
constexpr long HB_W1VH = HB_W1KL + NW_QKV1;
constexpr long HB_W1VL = HB_W1VH + NW_QKV1;
constexpr long HB_W1OH = HB_W1VL + NW_QKV1;
constexpr long HB_W1OL = HB_W1OH + NW_O;
constexpr long HB_W1FH = HB_W1OL + NW_O;
constexpr long HB_W1FL = HB_W1FH + NW_F;
constexpr long HB_W2QH = HB_W1FL + NW_F;
constexpr long HB_W2QL = HB_W2QH + NW_QKV2;
constexpr long HB_W2KH = HB_W2QL + NW_QKV2;
constexpr long HB_W2KL = HB_W2KH + NW_QKV2;
constexpr long HB_W2VH = HB_W2KL + NW_QKV2;
constexpr long HB_W2VL = HB_W2VH + NW_QKV2;
constexpr long HB_W2OH = HB_W2VL + NW_QKV2;
constexpr long HB_W2OL = HB_W2OH + NW_O;
constexpr long HB_W2FH = HB_W2OL + NW_O;
constexpr long HB_W2FL = HB_W2FH + NW_F;
constexpr long HB_END  = HB_W2FL + NW_F;

constexpr long SCRATCH_TOT = F32_END + (HB_END + 1) / 2 + 64;
__device__ float g_scratch[SCRATCH_TOT];

// ---------------- helpers ----------------
__device__ __forceinline__ void f2hilo(float v, __nv_bfloat16& h, __nv_bfloat16& l) {
    h = __float2bfloat16(v);
    l = __float2bfloat16(v - __bfloat162float(h));
}

__device__ __forceinline__ void cp16(uint32_t d, const void* s) {
    asm volatile("cp.async.cg.shared.global [%0], [%1], 16;\n" :: "r"(d), "l"(s));
}

#define MMA16816(c, a, b0, b1)                                              \
    asm volatile("mma.sync.aligned.m16n8k16.row.col.f32.bf16.bf16.f32 "     \
                 "{%0,%1,%2,%3},{%4,%5,%6,%7},{%8,%9},{%0,%1,%2,%3};"       \
                 : "+f"((c)[0]), "+f"((c)[1]), "+f"((c)[2]), "+f"((c)[3])   \
                 : "r"((a)[0]), "r"((a)[1]), "r"((a)[2]), "r"((a)[3]),      \
                   "r"(b0), "r"(b1))

// ---------------- positional encoding ----------------
__global__ void posgen_kernel(float* __restrict__ pos) {
    int idx = blockIdx.x * blockDim.x + threadIdx.x;
    if (idx >= CS * CE) return;
    int s = idx >> 9;
    int e = idx & 511;
    int m = e >> 1;
    double ang = (m >= 128) ? ((double)s / 10000.0) : (double)s;
    pos[idx] = (e & 1) ? (float)cos(ang) : (float)sin(ang);
}

__global__ void addpos_hilo(const float* __restrict__ X,
                            const float* __restrict__ pos,
                            float* __restrict__ xp,
                            __nv_bfloat16* __restrict__ xh,
                            __nv_bfloat16* __restrict__ xl, long n) {
    long idx = (long)blockIdx.x * blockDim.x + threadIdx.x;
    if (idx >= n) return;
    float v = X[idx] + pos[idx % (CS * CE)];
    xp[idx] = v;
    f2hilo(v, xh[idx], xl[idx]);
}

// ---------------- transpose + hi/lo convert ----------------
// in: [Z][R][C] f32; out: [Z][C][R] bf16 hi/lo
__global__ void transpose_hilo(const float* __restrict__ in,
                               __nv_bfloat16* __restrict__ oh,
                               __nv_bfloat16* __restrict__ ol,
                               int R, int C) {
    __shared__ float t[32][33];
    long zo = (long)blockIdx.z * R * C;
    int c0 = blockIdx.x * 32, r0 = blockIdx.y * 32;
    int tx = threadIdx.x, ty = threadIdx.y;
    #pragma unroll
    for (int i = 0; i < 32; i += 8)
        t[ty + i][tx] = in[zo + (long)(r0 + ty + i) * C + c0 + tx];
    __syncthreads();
    #pragma unroll
    for (int i = 0; i < 32; i += 8) {
        float v = t[tx][ty + i];
        long o = zo + (long)(c0 + ty + i) * R + r0 + tx;
        __nv_bfloat16 h, l;
        f2hilo(v, h, l);
        oh[o] = h; ol[o] = l;
    }
}

// ---------------- 3xBF16 tensor-core GEMM ----------------
// C = alpha * A @ B^T(+bias)(+tanh). A: [M][K] hi/lo bf16. B: [N][K] hi/lo bf16.
// OUTMODE: 0 = f32 out, 1 = hi/lo bf16 out.
// CTA 128x128, BK=32, 4 warps (each 64x64), double-buffered cp.async.
#define GSMEM 81920   // 2 stages * 4 tiles * 128 rows * 80B

template<int OUTMODE, bool TANH>
__global__ void __launch_bounds__(128, 2) gemm3(
    const __nv_bfloat16* __restrict__ Ah, const __nv_bfloat16* __restrict__ Al,
    const __nv_bfloat16* __restrict__ Bh, const __nv_bfloat16* __restrict__ Bl,
    const float* __restrict__ biasb,
    float* __restrict__ Cf,
    __nv_bfloat16* __restrict__ Ch, __nv_bfloat16* __restrict__ Cl,
    int K, int lda, int ldb, int ldc, int Hdiv,
    long sA_b, long sA_h, long sB_b, long sB_h,
    long sC_b, long sC_h, long sBias_h, float alpha)
{
    extern __shared__ uint8_t smem[];
    int z = blockIdx.z, zb = z / Hdiv, zh_ = z - zb * Hdiv;
    const __nv_bfloat16* Ahp = Ah + zb * sA_b + zh_ * sA_h;
    const __nv_bfloat16* Alp = Al + zb * sA_b + zh_ * sA_h;
    const __nv_bfloat16* Bhp = Bh + zb * sB_b + zh_ * sB_h;
    const __nv_bfloat16* Blp = Bl + zb * sB_b + zh_ * sB_h;
    int m0 = blockIdx.y * 128, n0 = blockIdx.x * 128;
    int tid = threadIdx.x;
    int wid = tid >> 5, lane = tid & 31;
    int g = lane >> 2, tig = lane & 3;
    int wm = (wid & 1) * 64, wn = (wid >> 1) * 64;

    uint32_t sbase = (uint32_t)__cvta_generic_to_shared(smem);

    float acc[4][8][4];
    #pragma unroll
    for (int i = 0; i < 4; ++i)
        #pragma unroll
        for (int j = 0; j < 8; ++j)
            #pragma unroll
            for (int q = 0; q < 4; ++q) acc[i][j][q] = 0.f;

    const __nv_bfloat16* ga_h = Ahp + (long)(m0 + tid) * lda;
    const __nv_bfloat16* ga_l = Alp + (long)(m0 + tid) * lda;
    const __nv_bfloat16* gb_h = Bhp + (long)(n0 + tid) * ldb;
    const __nv_bfloat16* gb_l = Blp + (long)(n0 + tid) * ldb;

    int nk = K / 32;
    // prologue: load chunk 0 into stage 0
    {
        uint32_t d = sbase + tid * 80;
        #pragma unroll
        for (int c = 0; c < 4; ++c) {
            cp16(d + c * 16,         ga_h + c * 8);
            cp16(d + 10240 + c * 16, ga_l + c * 8);
            cp16(d + 20480 + c * 16, gb_h + c * 8);
            cp16(d + 30720 + c * 16, gb_l + c * 8);
        }
        asm volatile("cp.async.commit_group;");
    }

    for (int kc = 0; kc < nk; ++kc) {
        if (kc + 1 < nk) {
            int k0 = (kc + 1) * 32;
            uint32_t d = sbase + ((kc + 1) & 1) * 40960 + tid * 80;
            #pragma unroll
            for (int c = 0; c < 4; ++c) {
                cp16(d + c * 16,         ga_h + k0 + c * 8);
                cp16(d + 10240 + c * 16, ga_l + k0 + c * 8);
                cp16(d + 20480 + c * 16, gb_h + k0 + c * 8);
                cp16(d + 30720 + c * 16, gb_l + k0 + c * 8);
            }
            asm volatile("cp.async.commit_group;");
            asm volatile("cp.async.wait_group 1;");
        } else {
            asm volatile("cp.async.wait_group 0;");
        }
        __syncthreads();

        const uint8_t* sb_ = smem + (kc & 1) * 40960;
        #pragma unroll
        for (int ks = 0; ks < 2; ++ks) {
            int cb = ks * 32 + tig * 4;
            uint32_t ah[4][4], al2[4][4];
            #pragma unroll
            for (int mt = 0; mt < 4; ++mt) {
                const uint8_t* p = sb_ + (wm + mt * 16 + g) * 80 + cb;
                ah[mt][0] = *(const uint32_t*)(p);
                ah[mt][1] = *(const uint32_t*)(p + 8 * 80);
                ah[mt][2] = *(const uint32_t*)(p + 16);
                ah[mt][3] = *(const uint32_t*)(p + 8 * 80 + 16);
                const uint8_t* q_ = p + 10240;
                al2[mt][0] = *(const uint32_t*)(q_);
                al2[mt][1] = *(const uint32_t*)(q_ + 8 * 80);
                al2[mt][2] = *(const uint32_t*)(q_ + 16);
                al2[mt][3] = *(const uint32_t*)(q_ + 8 * 80 + 16);
            }
            #pragma unroll
            for (int nt = 0; nt < 8; ++nt) {
                const uint8_t* pb = sb_ + 20480 + (wn + nt * 8 + g) * 80 + cb;
                uint32_t bh0 = *(const uint32_t*)(pb);
                uint32_t bh1 = *(const uint32_t*)(pb + 16);
                uint32_t bl0 = *(const uint32_t*)(pb + 10240);
                uint32_t bl1 = *(const uint32_t*)(pb + 10240 + 16);
                #pragma unroll
                for (int mt = 0; mt < 4; ++mt) {
                    MMA16816(acc[mt][nt], ah[mt], bh0, bh1);   // hi*hi
                    MMA16816(acc[mt][nt], al2[mt], bh0, bh1);  // lo*hi
                    MMA16816(acc[mt][nt], ah[mt], bl0, bl1);   // hi*lo
                }
            }
        }
        __syncthreads();
    }

    // epilogue
    float* Cfp = nullptr;
    __nv_bfloat16 *Chp = nullptr, *Clp = nullptr;
    if (OUTMODE == 0) Cfp = Cf + zb * sC_b + zh_ * sC_h;
    else { Chp = Ch + zb * sC_b + zh_ * sC_h; Clp = Cl + zb * sC_b + zh_ * sC_h; }
    const float* bias = biasb ? biasb + (long)zh_ * sBias_h : nullptr;

    #pragma unroll
    for (int nt = 0; nt < 8; ++nt) {
        int col = n0 + wn + nt * 8 + tig * 2;
        float bb0 = 0.f, bb1 = 0.f;
        if (bias) { bb0 = bias[col]; bb1 = bias[col + 1]; }
        #pragma unroll
        for (int mt = 0; mt < 4; ++mt) {
            int r0 = m0 + wm + mt * 16 + g;
            float v00 = acc[mt][nt][0] * alpha + bb0;
            float v01 = acc[mt][nt][1] * alpha + bb1;
            float v10 = acc[mt][nt][2] * alpha + bb0;
            float v11 = acc[mt][nt][3] * alpha + bb1;
            if (TANH) { v00 = tanhf(v00); v01 = tanhf(v01); v10 = tanhf(v10); v11 = tanhf(v11); }
            if (OUTMODE == 0) {
                *(float2*)(Cfp + (long)r0 * ldc + col) = make_float2(v00, v01);
                *(float2*)(Cfp + (long)(r0 + 8) * ldc + col) = make_float2(v10, v11);
            } else {
                __nv_bfloat16 h0, l0, h1, l1;
                f2hilo(v00, h0, l0); f2hilo(v01, h1, l1);
                __nv_bfloat162 hh; hh.x = h0; hh.y = h1;
                __nv_bfloat162 ll; ll.x = l0; ll.y = l1;
                *(__nv_bfloat162*)(Chp + (long)r0 * ldc + col) = hh;
                *(__nv_bfloat162*)(Clp + (long)r0 * ldc + col) = ll;
                f2hilo(v10, h0, l0); f2hilo(v11, h1, l1);
                hh.x = h0; hh.y = h1; ll.x = l0; ll.y = l1;
                *(__nv_bfloat162*)(Chp + (long)(r0 + 8) * ldc + col) = hh;
                *(__nv_bfloat162*)(Clp + (long)(r0 + 8) * ldc + col) = ll;
            }
        }
    }
}

// ---------------- softmax over the QUERY axis, hi/lo output ----------------
__global__ void softmax_q_hilo(const float* __restrict__ Sc,
                               __nv_bfloat16* __restrict__ oh,
                               __nv_bfloat16* __restrict__ ol) {
    long base = (long)blockIdx.x * CS * CS;
    const float* p = Sc + base;
    int t = threadIdx.x;
    float m = -1e30f, l = 0.f;
    for (int s = 0; s < CS; ++s) {
        float x = p[(long)s * CS + t];
        float nm = fmaxf(m, x);
        l = l * __expf(m - nm) + __expf(x - nm);
        m = nm;
    }
    float inv = 1.f / l;
    for (int s = 0; s < CS; ++s) {
        float e = __expf(p[(long)s * CS + t] - m) * inv;
        __nv_bfloat16 h, lo;
        f2hilo(e, h, lo);
        oh[base + (long)s * CS + t] = h;
        ol[base + (long)s * CS + t] = lo;
    }
}

// ---------------- batch-norm over batch axis, fused residual add ----------
template<bool HILO>
__global__ void bn_kernel(const float* __restrict__ x,
                          const float* __restrict__ add, int addw,
                          float* __restrict__ out,
                          __nv_bfloat16* __restrict__ oh,
                          __nv_bfloat16* __restrict__ ol) {
    int j = blockIdx.x * blockDim.x + threadIdx.x;
    if (j >= CS * CD2) return;
    const long SD = (long)CS * CD2;
    int s = j >> 10;
    int e = j & 1023;
    int ae = e & (addw - 1);
    long aoff = (long)s * addw + ae;

    float v[CB];
    float sum = 0.f;
    #pragma unroll
    for (int b = 0; b < CB; ++b) {
        float t = x[(long)b * SD + j] + add[(long)b * CS * addw + aoff];
        v[b] = t;
        sum += t;
    }
    float mean = sum * (1.f / CB);
    float var = 0.f;
    #pragma unroll
    for (int b = 0; b < CB; ++b) {
        float d = v[b] - mean;
        var += d * d;
    }
    var *= (1.f / CB);
    float rstd = rsqrtf(var + 1e-3f);
    #pragma unroll
    for (int b = 0; b < CB; ++b) {
        float o = (v[b] - mean) * rstd;
        out[(long)b * SD + j] = o;
        if (HILO) {
            __nv_bfloat16 h, l;
            f2hilo(o, h, l);
            oh[(long)b * SD + j] = h;
            ol[(long)b * SD + j] = l;
        }
    }
}

// ---------------- host orchestration ----------------
struct Ptrs {
    float* f32;
    __nv_bfloat16* hb;
};

static void run_attn(int Din,
                     const __nv_bfloat16* xh, const __nv_bfloat16* xl,
                     const __nv_bfloat16* WqTh, const __nv_bfloat16* WqTl,
                     const __nv_bfloat16* WkTh, const __nv_bfloat16* WkTl,
                     const __nv_bfloat16* WvTh, const __nv_bfloat16* WvTl,
                     const float* bq, const float* bk, const float* bv,
                     const __nv_bfloat16* WoTh, const __nv_bfloat16* WoTl,
                     const float* bo, Ptrs p, float* aout)
{
    float* v  = p.f32 + OF_V;
    float* sc = p.f32 + OF_SC;
    __nv_bfloat16 *qh = p.hb + HB_QH, *ql = p.hb + HB_QL;
    __nv_bfloat16 *kh = p.hb + HB_KH, *kl = p.hb + HB_KL;
    __nv_bfloat16 *vth = p.hb + HB_VTH, *vtl = p.hb + HB_VTL;
    __nv_bfloat16 *ath = p.hb + HB_ATH, *atl = p.hb + HB_ATL;
    __nv_bfloat16 *zh = p.hb + HB_ZH, *zl = p.hb + HB_ZL;

    long sAb = (long)CS * Din, sBh = (long)CDK * Din;
    long sCb = (long)CH * CS * CDK, sCh = (long)CS * CDK;
    dim3 gq(1, CS / 128, CB * CH);
    // Q, K (hi/lo out), V (f32 out for transpose)
    gemm3<1, false><<<gq, 128, GSMEM>>>(xh, xl, WqTh, WqTl, bq, nullptr, qh, ql,
        Din, Din, Din, CDK, CH, sAb, 0, 0, sBh, sCb, sCh, CDK, 1.f);
    gemm3<1, false><<<gq, 128, GSMEM>>>(xh, xl, WkTh, WkTl, bk, nullptr, kh, kl,
        Din, Din, Din, CDK, CH, sAb, 0, 0, sBh, sCb, sCh, CDK, 1.f);
    gemm3<0, false><<<gq, 128, GSMEM>>>(xh, xl, WvTh, WvTl, bv, v, nullptr, nullptr,
        Din, Din, Din, CDK, CH, sAb, 0, 0, sBh, sCb, sCh, CDK, 1.f);

    // V transpose+convert: [z][t][dk] -> [z][dk][t]
    transpose_hilo<<<dim3(CDK / 32, CS / 32, CB * CH), dim3(32, 8)>>>(v, vth, vtl, CS, CDK);

    // scores = Q @ K^T * 1/sqrt(dk)  (A=[s][dk], B=[t][dk])
    gemm3<0, false><<<dim3(CS / 128, CS / 128, CB * CH), 128, GSMEM>>>(
        qh, ql, kh, kl, nullptr, sc, nullptr, nullptr,
        CDK, CDK, CDK, CS, 1,
        (long)CS * CDK, 0, (long)CS * CDK, 0, (long)CS * CS, 0, 0,
        0.08838834764831845f);

    // softmax over query axis -> attn hi/lo
    softmax_q_hilo<<<CB * CH, CS>>>(sc, ath, atl);

    // z = attn @ V  (B = V^T [dk][t]); write in (b,s,h*128+c) layout
    gemm3<1, false><<<dim3(1, CS / 128, CB * CH), 128, GSMEM>>>(
        ath, atl, vth, vtl, nullptr, nullptr, zh, zl,
        CS, CS, CS, CHD, CH,
        (long)CH * CS * CS, (long)CS * CS,
        (long)CH * CDK * CS, (long)CDK * CS,
        (long)CS * CHD, CDK, 0, 1.f);

    // out projection: (B*S,768) @ (768,1024)
    gemm3<0, false><<<dim3(CD2 / 128, (CB * CS) / 128, 1), 128, GSMEM>>>(
        zh, zl, WoTh, WoTl, bo, aout, nullptr, nullptr,
        CHD, CHD, CHD, CD2, 1, 0, 0, 0, 0, 0, 0, 0, 1.f);
}

extern "C" void kernel_launch(void* const* d_in, const int* in_sizes, int n_in,
                              void* d_out, int out_size)
{
    const float* X    = (const float*)d_in[0];
    const float* Wq1  = (const float*)d_in[1];
    const float* Wk1  = (const float*)d_in[2];
    const float* Wv1  = (const float*)d_in[3];
    const float* bq1  = (const float*)d_in[4];
    const float* bk1  = (const float*)d_in[5];
    const float* bv1  = (const float*)d_in[6];
    const float* Wo1  = (const float*)d_in[7];
    const float* bo1  = (const float*)d_in[8];
    const float* Wff1 = (const float*)d_in[9];
    const float* bff1 = (const float*)d_in[10];
    const float* Wq2  = (const float*)d_in[11];
    const float* Wk2  = (const float*)d_in[12];
    const float* Wv2  = (const float*)d_in[13];
    const float* bq2  = (const float*)d_in[14];
    const float* bk2  = (const float*)d_in[15];
    const float* bv2  = (const float*)d_in[16];
    const float* Wo2  = (const float*)d_in[17];
    const float* bo2  = (const float*)d_in[18];
    const float* Wff2 = (const float*)d_in[19];
    const float* bff2 = (const float*)d_in[20];
    float* out = (float*)d_out;

    static_assert(SCRATCH_TOT > 0, "");
    float* sb = nullptr;
    cudaGetSymbolAddress((void**)&sb, g_scratch);
    Ptrs p;
    p.f32 = sb;
    p.hb = (__nv_bfloat16*)(sb + F32_END);

    // opt-in large dynamic smem
    cudaFuncSetAttribute(gemm3<0, false>, cudaFuncAttributeMaxDynamicSharedMemorySize, GSMEM);
    cudaFuncSetAttribute(gemm3<0, true>,  cudaFuncAttributeMaxDynamicSharedMemorySize, GSMEM);
    cudaFuncSetAttribute(gemm3<1, false>, cudaFuncAttributeMaxDynamicSharedMemorySize, GSMEM);

    // ----- weight transpose + hi/lo convert -----
    dim3 tb(32, 8);
    transpose_hilo<<<dim3(CDK/32, CE/32, CH),   tb>>>(Wq1, p.hb+HB_W1QH, p.hb+HB_W1QL, CE,  CDK);
    transpose_hilo<<<dim3(CDK/32, CE/32, CH),   tb>>>(Wk1, p.hb+HB_W1KH, p.hb+HB_W1KL, CE,  CDK);
    transpose_hilo<<<dim3(CDK/32, CE/32, CH),   tb>>>(Wv1, p.hb+HB_W1VH, p.hb+HB_W1VL, CE,  CDK);
    transpose_hilo<<<dim3(CD2/32, CHD/32, 1),   tb>>>(Wo1, p.hb+HB_W1OH, p.hb+HB_W1OL, CHD, CD2);
    transpose_hilo<<<dim3(CD2/32, CD2/32, 1),   tb>>>(Wff1,p.hb+HB_W1FH, p.hb+HB_W1FL, CD2, CD2);
    transpose_hilo<<<dim3(CDK/32, CD2/32, CH),  tb>>>(Wq2, p.hb+HB_W2QH, p.hb+HB_W2QL, CD2, CDK);
    transpose_hilo<<<dim3(CDK/32, CD2/32, CH),  tb>>>(Wk2, p.hb+HB_W2KH, p.hb+HB_W2KL, CD2, CDK);
    transpose_hilo<<<dim3(CDK/32, CD2/32, CH),  tb>>>(Wv2, p.hb+HB_W2VH, p.hb+HB_W2VL, CD2, CDK);
    transpose_hilo<<<dim3(CD2/32, CHD/32, 1),   tb>>>(Wo2, p.hb+HB_W2OH, p.hb+HB_W2OL, CHD, CD2);
    transpose_hilo<<<dim3(CD2/32, CD2/32, 1),   tb>>>(Wff2,p.hb+HB_W2FH, p.hb+HB_W2FL, CD2, CD2);

    // ----- positional encoding -----
    float* pos = sb + OF_POS;
    float* xp  = sb + OF_XP;
    posgen_kernel<<<(CS * CE + 255) / 256, 256>>>(pos);
    long nxp = NB_XP;
    addpos_hilo<<<(unsigned)((nxp + 255) / 256), 256>>>(X, pos, xp,
        p.hb + HB_XPH, p.hb + HB_XPL, nxp);

    float* a  = sb + OF_A;
    float* n1 = sb + OF_N1;
    float* n2 = sb + OF_N2;
    float* n3 = sb + OF_N3;
    float* f  = sb + OF_F;
    int nbn = (CS * CD2 + 255) / 256;
    dim3 gff(CD2 / 128, (CB * CS) / 128, 1);

    // ----- block 1: attention (Din = 512) -----
    run_attn(CE, p.hb + HB_XPH, p.hb + HB_XPL,
             p.hb+HB_W1QH, p.hb+HB_W1QL, p.hb+HB_W1KH, p.hb+HB_W1KL,
             p.hb+HB_W1VH, p.hb+HB_W1VL, bq1, bk1, bv1,
             p.hb+HB_W1OH, p.hb+HB_W1OL, bo1, p, a);
    bn_kernel<true><<<nbn, 256>>>(a, xp, CE, n1, p.hb + HB_N1H, p.hb + HB_N1L);

    // ----- block 2: FFN -----
    gemm3<0, true><<<gff, 128, GSMEM>>>(
        p.hb + HB_N1H, p.hb + HB_N1L, p.hb + HB_W1FH, p.hb + HB_W1FL, bff1,
        f, nullptr, nullptr, CD2, CD2, CD2, CD2, 1, 0, 0, 0, 0, 0, 0, 0, 1.f);
    bn_kernel<true><<<nbn, 256>>>(f, n1, CD2, n2, p.hb + HB_N2H, p.hb + HB_N2L);

    // ----- block 3: attention (Din = 1024) -----
    run_attn(CD2, p.hb + HB_N2H, p.hb + HB_N2L,
             p.hb+HB_W2QH, p.hb+HB_W2QL, p.hb+HB_W2KH, p.hb+HB_W2KL,
             p.hb+HB_W2VH, p.hb+HB_W2VL, bq2, bk2, bv2,
             p.hb+HB_W2OH, p.hb+HB_W2OL, bo2, p, a);
    bn_kernel<true><<<nbn, 256>>>(a, n2, CD2, n3, p.hb + HB_N3H, p.hb + HB_N3L);

    // ----- block 4: FFN -----
    gemm3<0, true><<<gff, 128, GSMEM>>>(
        p.hb + HB_N3H, p.hb + HB_N3L, p.hb + HB_W2FH, p.hb + HB_W2FL, bff2,
        f, nullptr, nullptr, CD2, CD2, CD2, CD2, 1, 0, 0, 0, 0, 0, 0, 0, 1.f);
    bn_kernel<false><<<nbn, 256>>>(f, n3, CD2, out, nullptr, nullptr);
}